// round 15
// baseline (speedup 1.0000x reference)
#include <cuda_runtime.h>
#include <cuda_fp16.h>
#include <math.h>
#include <stdint.h>

// Problem constants
#define T_SEQ 2048
#define HH 16
#define MTOT 8192        // B*T
#define KDIM 2048        // C
#define NY 6176          // 2048 (qk) + 4096 (vg) + 16 (a) + 16 (b)
#define NYPAD2 6400      // 25 * 256
#define SCALE_Q 0.125f   // DK^-0.5

// ------------------------- scratch (static device globals) -------------------
static __device__ float g_y[(size_t)MTOT * NY];
static __device__ float g_qT[(size_t)64 * 2048 * 64];
static __device__ float g_kT[(size_t)64 * 2048 * 64];
static __device__ float g_vT[(size_t)64 * 2048 * 128];
static __device__ float g_beta[64 * 2048];
static __device__ float g_gdec[64 * 2048];
static __device__ float g_o[(size_t)MTOT * 2048];
// fp16 operands: A-side split hi/lo, B-side hi only
static __device__ __half g_xh[(size_t)MTOT * KDIM];
static __device__ __half g_xl[(size_t)MTOT * KDIM];
static __device__ __half g_wh[(size_t)NYPAD2 * KDIM];
static __device__ __half g_owh[(size_t)2048 * KDIM];
static __device__ __half g_oh[(size_t)MTOT * 2048];
static __device__ __half g_ol[(size_t)MTOT * 2048];

__device__ __forceinline__ float siluf(float x) { return x / (1.f + expf(-x)); }

__device__ __forceinline__ void split4h(float4 v, uint2& hi, uint2& lo) {
    float f[4] = {v.x, v.y, v.z, v.w};
    __half h[4], l[4];
    #pragma unroll
    for (int i = 0; i < 4; ++i) {
        h[i] = __float2half_rn(f[i]);
        l[i] = __float2half_rn(f[i] - __half2float(h[i]));
    }
    __half2 h01 = __halves2half2(h[0], h[1]), h23 = __halves2half2(h[2], h[3]);
    __half2 l01 = __halves2half2(l[0], l[1]), l23 = __halves2half2(l[2], l[3]);
    hi.x = *(unsigned*)&h01; hi.y = *(unsigned*)&h23;
    lo.x = *(unsigned*)&l01; lo.y = *(unsigned*)&l23;
}
__device__ __forceinline__ uint2 pack4h(float4 v) {
    __half2 h01 = __halves2half2(__float2half_rn(v.x), __float2half_rn(v.y));
    __half2 h23 = __halves2half2(__float2half_rn(v.z), __float2half_rn(v.w));
    uint2 r; r.x = *(unsigned*)&h01; r.y = *(unsigned*)&h23; return r;
}

// ------------------------- conversion kernels --------------------------------
__global__ void __launch_bounds__(256) cvt_x(const float* __restrict__ x) {
    int idx4 = blockIdx.x * 256 + threadIdx.x;
    float4 v = *(const float4*)(x + (size_t)idx4 * 4);
    uint2 hi, lo; split4h(v, hi, lo);
    *(uint2*)(g_xh + (size_t)idx4 * 4) = hi;
    *(uint2*)(g_xl + (size_t)idx4 * 4) = lo;
}

__global__ void __launch_bounds__(256) cvt_w(
    const float* __restrict__ B0, const float* __restrict__ B1,
    const float* __restrict__ B2, const float* __restrict__ B3) {
    int idx4 = blockIdx.x * 256 + threadIdx.x;           // over NYPAD2*KDIM/4
    int n = idx4 >> 9;
    int col = (idx4 & 511) * 4;
    float4 v = make_float4(0.f, 0.f, 0.f, 0.f);
    const float* bp;
    if (n < 2048)       bp = B0 + (size_t)n * KDIM;
    else if (n < 6144)  bp = B1 + (size_t)(n - 2048) * KDIM;
    else if (n < 6160)  bp = B2 + (size_t)(n - 6144) * KDIM;
    else if (n < 6176)  bp = B3 + (size_t)(n - 6160) * KDIM;
    else                bp = (const float*)0;
    if (bp) v = *(const float4*)(bp + col);
    *(uint2*)(g_wh + (size_t)idx4 * 4) = pack4h(v);
}

__global__ void __launch_bounds__(256) cvt_ow(const float* __restrict__ ow) {
    int idx4 = blockIdx.x * 256 + threadIdx.x;
    float4 v = *(const float4*)(ow + (size_t)idx4 * 4);
    *(uint2*)(g_owh + (size_t)idx4 * 4) = pack4h(v);
}

// ============================ HMMA fp16x2 GEMM ===============================
// C[m][n] = sum_k A[m][k] * Brow(n)[k]; A = hi+lo fp16, B = hi fp16.
// CTA 128x256, K-tile 64, 8 warps as 2(m) x 4(n), warp tile 64x64.
// 3-stage cp.async pipeline, ldmatrix fragments.
// wm=1 warps process k16 blocks in rotated order (2,3,0,1) so the two warps
// sharing each SMSP overlap LDSM bursts with MMA bursts.
#define HBK 64
#define HNKT (KDIM / HBK)
#define ROWB 144                          // bytes per 64-half tile row (pad)
#define OFF_AL (128 * ROWB)               // 18432
#define OFF_BH (2 * 128 * ROWB)           // 36864
#define STAGEB (OFF_BH + 256 * ROWB)      // 73728
#define NSTAGE 3
#define GSMEM (NSTAGE * STAGEB)           // 221184

__device__ __forceinline__ void mma16816(float d[4], const unsigned a[4],
                                         unsigned b0, unsigned b1) {
    asm volatile(
        "mma.sync.aligned.m16n8k16.row.col.f32.f16.f16.f32 "
        "{%0,%1,%2,%3},{%4,%5,%6,%7},{%8,%9},{%0,%1,%2,%3};\n"
        : "+f"(d[0]), "+f"(d[1]), "+f"(d[2]), "+f"(d[3])
        : "r"(a[0]), "r"(a[1]), "r"(a[2]), "r"(a[3]), "r"(b0), "r"(b1));
}
__device__ __forceinline__ void cp16(uint32_t dst, const void* src) {
    asm volatile("cp.async.cg.shared.global [%0], [%1], 16;" :: "r"(dst), "l"(src) : "memory");
}
#define CP_COMMIT() asm volatile("cp.async.commit_group;" ::: "memory")
#define CP_WAIT(n)  asm volatile("cp.async.wait_group %0;" :: "n"(n) : "memory")
#define LDSM4(r, a) \
    asm volatile("ldmatrix.sync.aligned.m8n8.x4.shared.b16 {%0,%1,%2,%3}, [%4];" \
                 : "=r"((r)[0]), "=r"((r)[1]), "=r"((r)[2]), "=r"((r)[3]) : "r"(a))
__device__ __forceinline__ uint32_t smem_u32(const void* p) {
    uint32_t a;
    asm("{ .reg .u64 t; cvta.to.shared.u64 t, %1; cvt.u32.u64 %0, t; }" : "=r"(a) : "l"(p));
    return a;
}

__global__ void __launch_bounds__(256, 1) gdn_gemm_h2(float* __restrict__ Cout, int Nc, int which)
{
    extern __shared__ __align__(16) char smem[];
    const uint32_t sb = smem_u32(smem);

    const __half *Ah, *Al, *Bh;
    float* Cp;
    if (which) { Ah = g_xh; Al = g_xl; Bh = g_wh;  Cp = g_y; }
    else       { Ah = g_oh; Al = g_ol; Bh = g_owh; Cp = Cout; }

    const int tid = threadIdx.x;
    const int lane = tid & 31, warp = tid >> 5;
    const int wm = warp >> 2, wn = warp & 3;     // 2(m) x 4(n) warp grid
    const int g = lane >> 2, tg = lane & 3;
    const int m0 = blockIdx.y * 128, n0 = blockIdx.x * 256;
    const int krot = wm * 2;                     // k16-block rotation per SMSP pair

    // staging map
    int arow[4], ach[4];                          // A: 4 x 16B chunks/thread
    #pragma unroll
    for (int i = 0; i < 4; ++i) {
        int idx = i * 256 + tid;
        arow[i] = idx >> 3;  ach[i] = (idx & 7) * 16;
    }
    int brow[8], bch[8];                          // B: 8 x 16B chunks/thread
    #pragma unroll
    for (int i = 0; i < 8; ++i) {
        int idx = i * 256 + tid;
        brow[i] = idx >> 3;  bch[i] = (idx & 7) * 16;
    }

    auto load_stage = [&](int s, int ko) {
        uint32_t base = sb + s * STAGEB;
        #pragma unroll
        for (int i = 0; i < 4; ++i) {
            uint32_t d = base + arow[i] * ROWB + ach[i];
            size_t ga = (size_t)(m0 + arow[i]) * KDIM + ko + (ach[i] >> 1);
            cp16(d, Ah + ga);
            cp16(d + OFF_AL, Al + ga);
        }
        #pragma unroll
        for (int i = 0; i < 8; ++i) {
            uint32_t d = base + brow[i] * ROWB + bch[i];
            size_t gb = (size_t)(n0 + brow[i]) * KDIM + ko + (bch[i] >> 1);
            cp16(d + OFF_BH, Bh + gb);
        }
        CP_COMMIT();
    };

    // ldmatrix per-lane offsets (bytes)
    const uint32_t aoff = (lane & 15) * ROWB + (lane >> 4) * 16;
    const uint32_t boff = ((lane & 7) + ((lane >> 4) & 1) * 8) * ROWB + ((lane >> 3) & 1) * 16;

    float acc[4][8][4];
    #pragma unroll
    for (int mt = 0; mt < 4; ++mt)
        #pragma unroll
        for (int nt = 0; nt < 8; ++nt)
            #pragma unroll
            for (int i = 0; i < 4; ++i) acc[mt][nt][i] = 0.f;

    load_stage(0, 0);
    load_stage(1, HBK);

    int sidx = 0;                                // kt % 3
    for (int kt = 0; kt < HNKT; ++kt) {
        if (kt + 1 < HNKT) CP_WAIT(1); else CP_WAIT(0);
        __syncthreads();
        if (kt + 2 < HNKT) {
            int ls = sidx + 2; if (ls >= NSTAGE) ls -= NSTAGE;
            load_stage(ls, (kt + 2) * HBK);
        }

        const uint32_t stg = sb + sidx * STAGEB;
        #pragma unroll
        for (int ks = 0; ks < 4; ++ks) {
            const int ksx = (ks + krot) & 3;      // staggered block order per wm
            const uint32_t kb = ksx * 32;         // byte offset of k16 block
            unsigned ah[4][4], al[4][4], bq[4][4];
            #pragma unroll
            for (int mt = 0; mt < 4; ++mt) {
                uint32_t a = stg + (wm * 64 + mt * 16) * ROWB + kb + aoff;
                LDSM4(ah[mt], a);
                LDSM4(al[mt], a + OFF_AL);
            }
            #pragma unroll
            for (int p = 0; p < 4; ++p)
                LDSM4(bq[p], stg + OFF_BH + (wn * 64 + p * 16) * ROWB + kb + boff);
            // pass 1: Ahi * Bhi  (32 independent MMAs)
            #pragma unroll
            for (int p = 0; p < 4; ++p)
                #pragma unroll
                for (int mt = 0; mt < 4; ++mt) {
                    mma16816(acc[mt][2 * p],     ah[mt], bq[p][0], bq[p][1]);
                    mma16816(acc[mt][2 * p + 1], ah[mt], bq[p][2], bq[p][3]);
                }
            // pass 2: Alo * Bhi  (32 independent MMAs)
            #pragma unroll
            for (int p = 0; p < 4; ++p)
                #pragma unroll
                for (int mt = 0; mt < 4; ++mt) {
                    mma16816(acc[mt][2 * p],     al[mt], bq[p][0], bq[p][1]);
                    mma16816(acc[mt][2 * p + 1], al[mt], bq[p][2], bq[p][3]);
                }
        }
        if (++sidx == NSTAGE) sidx = 0;
    }

    // epilogue: canonical C layout, float2 stores
    #pragma unroll
    for (int mt = 0; mt < 4; ++mt) {
        int r0 = m0 + wm * 64 + mt * 16 + g;
        #pragma unroll
        for (int nt = 0; nt < 8; ++nt) {
            int c0 = n0 + wn * 64 + nt * 8 + 2 * tg;
            if (c0 < Nc) {
                *(float2*)(Cp + (size_t)r0 * Nc + c0) =
                    make_float2(acc[mt][nt][0], acc[mt][nt][1]);
                *(float2*)(Cp + (size_t)(r0 + 8) * Nc + c0) =
                    make_float2(acc[mt][nt][2], acc[mt][nt][3]);
            }
        }
    }
}

// --------------------- conv + silu + l2norm + beta/g ------------------------
__global__ void __launch_bounds__(512) gdn_convgate(
    const float* __restrict__ qcw, const float* __restrict__ kcw, const float* __restrict__ vcw,
    const float* __restrict__ b_bias, const float* __restrict__ beta_bias,
    const float* __restrict__ A_log, const float* __restrict__ dt_bias)
{
    const int blk = blockIdx.x;
    const int b = blk >> 11, t = blk & 2047;
    const int tid = threadIdx.x;
    const int h = tid >> 5, lane = tid & 31;
    const size_t rowbase = (size_t)blk * NY;

    float qv[2], kv[2];
    float sq = 0.f, sk = 0.f;
    #pragma unroll
    for (int p = 0; p < 2; ++p) {
        int cl = h * 64 + lane + p * 32;
        float aq = 0.f, ak = 0.f;
        #pragma unroll
        for (int j = 0; j < 4; ++j) {
            int tt = t - 3 + j;
            if (tt >= 0) {
                size_t rb = (size_t)(b * 2048 + tt) * NY;
                aq = fmaf(qcw[cl * 4 + j], g_y[rb + cl], aq);
                ak = fmaf(kcw[cl * 4 + j], g_y[rb + 1024 + cl], ak);
            }
        }
        aq = siluf(aq); ak = siluf(ak);
        qv[p] = aq; kv[p] = ak;
        sq = fmaf(aq, aq, sq); sk = fmaf(ak, ak, sk);
    }
    #pragma unroll
    for (int off = 16; off; off >>= 1) {
        sq += __shfl_xor_sync(0xffffffffu, sq, off);
        sk += __shfl_xor_sync(0xffffffffu, sk, off);
    }
    float rq = rsqrtf(sq + 1e-6f) * SCALE_Q;
    float rk = rsqrtf(sk + 1e-6f);
    size_t qkbase = ((size_t)(b * 16 + h) * 2048 + t) * 64;
    g_qT[qkbase + lane]      = qv[0] * rq;
    g_qT[qkbase + lane + 32] = qv[1] * rq;
    g_kT[qkbase + lane]      = kv[0] * rk;
    g_kT[qkbase + lane + 32] = kv[1] * rk;

    size_t vbase = ((size_t)(b * 16 + h) * 2048 + t) * 128;
    #pragma unroll
    for (int p = 0; p < 4; ++p) {
        int d = lane + p * 32;
        int cl = h * 128 + d;
        float av = 0.f;
        #pragma unroll
        for (int j = 0; j < 4; ++j) {
            int tt = t - 3 + j;
            if (tt >= 0)
                av = fmaf(vcw[cl * 4 + j], g_y[(size_t)(b * 2048 + tt) * NY + 2048 + cl], av);
        }
        g_vT[vbase + d] = siluf(av);
    }

    if (tid < 16) {
        float za = g_y[rowbase + 6144 + tid] + dt_bias[tid];
        float sp = (za > 15.f) ? za : log1pf(expf(za));
        g_gdec[(b * 16 + tid) * 2048 + t] = -expf(A_log[tid]) * sp;
        float zb = g_y[rowbase + 6160 + tid] + b_bias[tid] + beta_bias[tid];
        g_beta[(b * 16 + tid) * 2048 + t] = 2.f / (1.f + expf(-zb));
    }
}

// ------------------------------ gated delta scan ----------------------------
// grid (8 dv-chunks of 16, 64 bh), 128 threads: vl = tid>>3 (16 cols), kr = tid&7.
#define STT 32
__global__ void __launch_bounds__(128) gdn_scan()
{
    const int chunk = blockIdx.x;   // 0..7
    const int bh = blockIdx.y;      // 0..63
    const int tid = threadIdx.x;    // 0..127
    const int vl = tid >> 3;        // 0..15
    const int kr = tid & 7;
    const int b = bh >> 4, h = bh & 15;

    __shared__ __align__(16) float sqm[STT][64];
    __shared__ __align__(16) float skm[STT][64];
    __shared__ __align__(16) float svm[STT][16];
    __shared__ __align__(16) float som[STT][16];
    __shared__ float seg[STT];
    __shared__ float sbe[STT];

    float S[8];
    #pragma unroll
    for (int i = 0; i < 8; ++i) S[i] = 0.f;

    const float* qbase = g_qT + (size_t)bh * 2048 * 64;
    const float* kbase = g_kT + (size_t)bh * 2048 * 64;
    const float* vbase = g_vT + (size_t)bh * 2048 * 128 + chunk * 16;
    const float* gbase = g_gdec + bh * 2048;
    const float* bbase = g_beta + bh * 2048;

    const int vr = tid >> 2, vc = (tid & 3) << 2;   // 32 rows x 4 float4s

    for (int tile = 0; tile < 2048 / STT; ++tile) {
        int t0 = tile * STT;
        #pragma unroll
        for (int i = 0; i < 4; ++i) {
            int idx = tid + i * 128;
            int qr = idx >> 4, qc = (idx & 15) << 2;
            *(float4*)&sqm[qr][qc] = *(const float4*)(qbase + (size_t)(t0 + qr) * 64 + qc);
            *(float4*)&skm[qr][qc] = *(const float4*)(kbase + (size_t)(t0 + qr) * 64 + qc);
        }
        *(float4*)&svm[vr][vc] = *(const float4*)(vbase + (size_t)(t0 + vr) * 128 + vc);
        if (tid < STT) {
            seg[tid] = expf(gbase[t0 + tid]);
            sbe[tid] = bbase[t0 + tid];
        }
        __syncthreads();

        #pragma unroll 4
        for (int ts = 0; ts < STT; ++ts) {
            float eg = seg[ts];
            float be = sbe[ts];
            float vv = svm[ts][vl];
            float4 k0 = *(const float4*)&skm[ts][kr * 8];
            float4 k1 = *(const float4*)&skm[ts][kr * 8 + 4];
            float4 q0 = *(const float4*)&sqm[ts][kr * 8];
            float4 q1 = *(const float4*)&sqm[ts][kr * 8 + 4];
            float kk[8] = {k0.x, k0.y, k0.z, k0.w, k1.x, k1.y, k1.z, k1.w};
            float qq[8] = {q0.x, q0.y, q0.z, q0.w, q1.x, q1.y, q1.z, q1.w};
            float mem = 0.f;
            #pragma unroll
            for (int r = 0; r < 8; ++r) {
                S[r] *= eg;
                mem = fmaf(kk[r], S[r], mem);
            }
            mem += __shfl_xor_sync(0xffffffffu, mem, 1);
            mem += __shfl_xor_sync(0xffffffffu, mem, 2);
            mem += __shfl_xor_sync(0xffffffffu, mem, 4);
            float delta = (vv - mem) * be;
            float ov = 0.f;
            #pragma unroll
            for (int r = 0; r < 8; ++r) {
                S[r] = fmaf(kk[r], delta, S[r]);
                ov = fmaf(qq[r], S[r], ov);
            }
            ov += __shfl_xor_sync(0xffffffffu, ov, 1);
            ov += __shfl_xor_sync(0xffffffffu, ov, 2);
            ov += __shfl_xor_sync(0xffffffffu, ov, 4);
            if (kr == 0) som[ts][vl] = ov;
        }
        __syncthreads();

        size_t orow = (size_t)(b * 2048 + t0 + vr) * 2048 + h * 128 + chunk * 16 + vc;
        *(float4*)(g_o + orow) = *(const float4*)&som[vr][vc];
        __syncthreads();
    }
}

// ---------------- RMS-norm over DV + silu(g_out) gate -> fp16 hi/lo ---------
__global__ void __launch_bounds__(256) gdn_normgate()
{
    int gw = blockIdx.x * 8 + (threadIdx.x >> 5);
    int lane = threadIdx.x & 31;
    int m = gw >> 4, h = gw & 15;
    size_t obase = (size_t)m * 2048 + h * 128;
    float v[4]; float ss = 0.f;
    #pragma unroll
    for (int p = 0; p < 4; ++p) {
        v[p] = g_o[obase + lane + p * 32];
        ss = fmaf(v[p], v[p], ss);
    }
    #pragma unroll
    for (int off = 16; off; off >>= 1) ss += __shfl_xor_sync(0xffffffffu, ss, off);
    float r = rsqrtf(ss * (1.f / 128.f) + 1.1920929e-7f);
    size_t ybase = (size_t)m * NY + 4096 + h * 128;
    #pragma unroll
    for (int p = 0; p < 4; ++p) {
        float gz = g_y[ybase + lane + p * 32];
        float val = v[p] * r * siluf(gz);
        __half hh = __float2half_rn(val);
        __half hl = __float2half_rn(val - __half2float(hh));
        g_oh[obase + lane + p * 32] = hh;
        g_ol[obase + lane + p * 32] = hl;
    }
}

// --------------------------------- launch -----------------------------------
extern "C" void kernel_launch(void* const* d_in, const int* in_sizes, int n_in,
                              void* d_out, int out_size)
{
    const float* x         = (const float*)d_in[0];
    const float* qk_w      = (const float*)d_in[1];
    const float* vg_w      = (const float*)d_in[2];
    const float* o_w       = (const float*)d_in[3];
    const float* a_w       = (const float*)d_in[4];
    const float* b_w       = (const float*)d_in[5];
    const float* b_bias    = (const float*)d_in[6];
    const float* beta_bias = (const float*)d_in[7];
    const float* A_log     = (const float*)d_in[8];
    const float* dt_bias   = (const float*)d_in[9];
    const float* qcw       = (const float*)d_in[10];
    const float* kcw       = (const float*)d_in[11];
    const float* vcw       = (const float*)d_in[12];
    float* out = (float*)d_out;

    cudaFuncSetAttribute(gdn_gemm_h2, cudaFuncAttributeMaxDynamicSharedMemorySize, GSMEM);

    // fp16 operand prep
    cvt_x<<<MTOT * KDIM / 4 / 256, 256>>>(x);
    cvt_w<<<NYPAD2 * KDIM / 4 / 256, 256>>>(qk_w, vg_w, a_w, b_w);
    cvt_ow<<<2048 * KDIM / 4 / 256, 256>>>(o_w);

    // GEMM1: y = x @ [qk_w; vg_w; a_w; b_w]^T
    dim3 g1(NYPAD2 / 256, MTOT / 128);
    gdn_gemm_h2<<<g1, 256, GSMEM>>>((float*)0, NY, 1);

    // conv + silu + per-head l2norm + beta/g
    gdn_convgate<<<MTOT, 512>>>(qcw, kcw, vcw, b_bias, beta_bias, A_log, dt_bias);

    // gated delta-rule scan
    dim3 gs(8, 64);
    gdn_scan<<<gs, 128>>>();

    // rms-norm + gate -> fp16 hi/lo
    gdn_normgate<<<MTOT * 16 / 8, 256>>>();

    // GEMM2: out = o @ o_w^T
    dim3 g2(2048 / 256, MTOT / 128);
    gdn_gemm_h2<<<g2, 256, GSMEM>>>(out, 2048, 0);
}

// round 16
// speedup vs baseline: 1.0193x; 1.0193x over previous
#include <cuda_runtime.h>
#include <cuda_fp16.h>
#include <math.h>
#include <stdint.h>

// Problem constants
#define T_SEQ 2048
#define HH 16
#define MTOT 8192        // B*T
#define KDIM 2048        // C
#define NY 6176          // 2048 (qk) + 4096 (vg) + 16 (a) + 16 (b)
#define NYPAD2 6400      // 25 * 256
#define SCALE_Q 0.125f   // DK^-0.5

// ------------------------- scratch (static device globals) -------------------
static __device__ float g_y[(size_t)MTOT * NY];
static __device__ float g_qT[(size_t)64 * 2048 * 64];
static __device__ float g_kT[(size_t)64 * 2048 * 64];
static __device__ float g_vT[(size_t)64 * 2048 * 128];
static __device__ float g_beta[64 * 2048];
static __device__ float g_gdec[64 * 2048];
static __device__ float g_o[(size_t)MTOT * 2048];
// fp16 operands: A-side split hi/lo, B-side hi only
static __device__ __half g_xh[(size_t)MTOT * KDIM];
static __device__ __half g_xl[(size_t)MTOT * KDIM];
static __device__ __half g_wh[(size_t)NYPAD2 * KDIM];
static __device__ __half g_owh[(size_t)2048 * KDIM];
static __device__ __half g_oh[(size_t)MTOT * 2048];
static __device__ __half g_ol[(size_t)MTOT * 2048];

__device__ __forceinline__ float siluf(float x) { return x / (1.f + expf(-x)); }

__device__ __forceinline__ void split4h(float4 v, uint2& hi, uint2& lo) {
    float f[4] = {v.x, v.y, v.z, v.w};
    __half h[4], l[4];
    #pragma unroll
    for (int i = 0; i < 4; ++i) {
        h[i] = __float2half_rn(f[i]);
        l[i] = __float2half_rn(f[i] - __half2float(h[i]));
    }
    __half2 h01 = __halves2half2(h[0], h[1]), h23 = __halves2half2(h[2], h[3]);
    __half2 l01 = __halves2half2(l[0], l[1]), l23 = __halves2half2(l[2], l[3]);
    hi.x = *(unsigned*)&h01; hi.y = *(unsigned*)&h23;
    lo.x = *(unsigned*)&l01; lo.y = *(unsigned*)&l23;
}
__device__ __forceinline__ uint2 pack4h(float4 v) {
    __half2 h01 = __halves2half2(__float2half_rn(v.x), __float2half_rn(v.y));
    __half2 h23 = __halves2half2(__float2half_rn(v.z), __float2half_rn(v.w));
    uint2 r; r.x = *(unsigned*)&h01; r.y = *(unsigned*)&h23; return r;
}

// ------------------------- conversion kernels --------------------------------
__global__ void __launch_bounds__(256) cvt_x(const float* __restrict__ x) {
    int idx4 = blockIdx.x * 256 + threadIdx.x;
    float4 v = *(const float4*)(x + (size_t)idx4 * 4);
    uint2 hi, lo; split4h(v, hi, lo);
    *(uint2*)(g_xh + (size_t)idx4 * 4) = hi;
    *(uint2*)(g_xl + (size_t)idx4 * 4) = lo;
}

__global__ void __launch_bounds__(256) cvt_w(
    const float* __restrict__ B0, const float* __restrict__ B1,
    const float* __restrict__ B2, const float* __restrict__ B3) {
    int idx4 = blockIdx.x * 256 + threadIdx.x;           // over NYPAD2*KDIM/4
    int n = idx4 >> 9;
    int col = (idx4 & 511) * 4;
    float4 v = make_float4(0.f, 0.f, 0.f, 0.f);
    const float* bp;
    if (n < 2048)       bp = B0 + (size_t)n * KDIM;
    else if (n < 6144)  bp = B1 + (size_t)(n - 2048) * KDIM;
    else if (n < 6160)  bp = B2 + (size_t)(n - 6144) * KDIM;
    else if (n < 6176)  bp = B3 + (size_t)(n - 6160) * KDIM;
    else                bp = (const float*)0;
    if (bp) v = *(const float4*)(bp + col);
    *(uint2*)(g_wh + (size_t)idx4 * 4) = pack4h(v);
}

__global__ void __launch_bounds__(256) cvt_ow(const float* __restrict__ ow) {
    int idx4 = blockIdx.x * 256 + threadIdx.x;
    float4 v = *(const float4*)(ow + (size_t)idx4 * 4);
    *(uint2*)(g_owh + (size_t)idx4 * 4) = pack4h(v);
}

// ============================ HMMA fp16x2 GEMM ===============================
// C[m][n] = sum_k A[m][k] * Brow(n)[k]; A = hi+lo fp16, B = hi fp16.
// CTA 128x256, K-tile 64, 16 warps (512 thr) as 2(m) x 8(n), warp tile 64x32.
// Small per-warp register footprint -> 4 warps/SMSP for latency hiding.
// 3-stage cp.async pipeline, ldmatrix fragments.
#define HBK 64
#define HNKT (KDIM / HBK)
#define ROWB 144                          // bytes per 64-half tile row (pad)
#define OFF_AL (128 * ROWB)               // 18432
#define OFF_BH (2 * 128 * ROWB)           // 36864
#define STAGEB (OFF_BH + 256 * ROWB)      // 73728
#define NSTAGE 3
#define GSMEM (NSTAGE * STAGEB)           // 221184

__device__ __forceinline__ void mma16816(float d[4], const unsigned a[4],
                                         unsigned b0, unsigned b1) {
    asm volatile(
        "mma.sync.aligned.m16n8k16.row.col.f32.f16.f16.f32 "
        "{%0,%1,%2,%3},{%4,%5,%6,%7},{%8,%9},{%0,%1,%2,%3};\n"
        : "+f"(d[0]), "+f"(d[1]), "+f"(d[2]), "+f"(d[3])
        : "r"(a[0]), "r"(a[1]), "r"(a[2]), "r"(a[3]), "r"(b0), "r"(b1));
}
__device__ __forceinline__ void cp16(uint32_t dst, const void* src) {
    asm volatile("cp.async.cg.shared.global [%0], [%1], 16;" :: "r"(dst), "l"(src) : "memory");
}
#define CP_COMMIT() asm volatile("cp.async.commit_group;" ::: "memory")
#define CP_WAIT(n)  asm volatile("cp.async.wait_group %0;" :: "n"(n) : "memory")
#define LDSM4(r, a) \
    asm volatile("ldmatrix.sync.aligned.m8n8.x4.shared.b16 {%0,%1,%2,%3}, [%4];" \
                 : "=r"((r)[0]), "=r"((r)[1]), "=r"((r)[2]), "=r"((r)[3]) : "r"(a))
__device__ __forceinline__ uint32_t smem_u32(const void* p) {
    uint32_t a;
    asm("{ .reg .u64 t; cvta.to.shared.u64 t, %1; cvt.u32.u64 %0, t; }" : "=r"(a) : "l"(p));
    return a;
}

__global__ void __launch_bounds__(512, 1) gdn_gemm_h2(float* __restrict__ Cout, int Nc, int which)
{
    extern __shared__ __align__(16) char smem[];
    const uint32_t sb = smem_u32(smem);

    const __half *Ah, *Al, *Bh;
    float* Cp;
    if (which) { Ah = g_xh; Al = g_xl; Bh = g_wh;  Cp = g_y; }
    else       { Ah = g_oh; Al = g_ol; Bh = g_owh; Cp = Cout; }

    const int tid = threadIdx.x;
    const int lane = tid & 31, warp = tid >> 5;
    const int wm = warp >> 3, wn = warp & 7;     // 2(m) x 8(n) warp grid
    const int g = lane >> 2, tg = lane & 3;
    const int m0 = blockIdx.y * 128, n0 = blockIdx.x * 256;

    // staging map (512 threads)
    int arow[2], ach[2];                          // A: 2 x 16B chunks/thread
    #pragma unroll
    for (int i = 0; i < 2; ++i) {
        int idx = i * 512 + tid;                  // 0..1023 over 128 rows x 8 chunks
        arow[i] = idx >> 3;  ach[i] = (idx & 7) * 16;
    }
    int brow[4], bch[4];                          // B: 4 x 16B chunks/thread
    #pragma unroll
    for (int i = 0; i < 4; ++i) {
        int idx = i * 512 + tid;                  // 0..2047 over 256 rows x 8 chunks
        brow[i] = idx >> 3;  bch[i] = (idx & 7) * 16;
    }

    auto load_stage = [&](int s, int ko) {
        uint32_t base = sb + s * STAGEB;
        #pragma unroll
        for (int i = 0; i < 2; ++i) {
            uint32_t d = base + arow[i] * ROWB + ach[i];
            size_t ga = (size_t)(m0 + arow[i]) * KDIM + ko + (ach[i] >> 1);
            cp16(d, Ah + ga);
            cp16(d + OFF_AL, Al + ga);
        }
        #pragma unroll
        for (int i = 0; i < 4; ++i) {
            uint32_t d = base + brow[i] * ROWB + bch[i];
            size_t gb = (size_t)(n0 + brow[i]) * KDIM + ko + (bch[i] >> 1);
            cp16(d + OFF_BH, Bh + gb);
        }
        CP_COMMIT();
    };

    // ldmatrix per-lane offsets (bytes)
    const uint32_t aoff = (lane & 15) * ROWB + (lane >> 4) * 16;
    const uint32_t boff = ((lane & 7) + ((lane >> 4) & 1) * 8) * ROWB + ((lane >> 3) & 1) * 16;

    float acc[4][4][4];
    #pragma unroll
    for (int mt = 0; mt < 4; ++mt)
        #pragma unroll
        for (int nt = 0; nt < 4; ++nt)
            #pragma unroll
            for (int i = 0; i < 4; ++i) acc[mt][nt][i] = 0.f;

    load_stage(0, 0);
    load_stage(1, HBK);

    int sidx = 0;                                // kt % 3
    for (int kt = 0; kt < HNKT; ++kt) {
        if (kt + 1 < HNKT) CP_WAIT(1); else CP_WAIT(0);
        __syncthreads();
        if (kt + 2 < HNKT) {
            int ls = sidx + 2; if (ls >= NSTAGE) ls -= NSTAGE;
            load_stage(ls, (kt + 2) * HBK);
        }

        const uint32_t stg = sb + sidx * STAGEB;
        #pragma unroll
        for (int ks = 0; ks < 4; ++ks) {
            const uint32_t kb = ks * 32;          // byte offset of k16 block
            unsigned bq[2][4];
            #pragma unroll
            for (int p = 0; p < 2; ++p)
                LDSM4(bq[p], stg + OFF_BH + (wn * 32 + p * 16) * ROWB + kb + boff);
            #pragma unroll
            for (int mt = 0; mt < 4; ++mt) {
                unsigned ah[4], al[4];
                uint32_t a = stg + (wm * 64 + mt * 16) * ROWB + kb + aoff;
                LDSM4(ah, a);
                LDSM4(al, a + OFF_AL);
                // hi pass for this mt (per-accumulator order: hi then lo per k16)
                mma16816(acc[mt][0], ah, bq[0][0], bq[0][1]);
                mma16816(acc[mt][1], ah, bq[0][2], bq[0][3]);
                mma16816(acc[mt][2], ah, bq[1][0], bq[1][1]);
                mma16816(acc[mt][3], ah, bq[1][2], bq[1][3]);
                // lo pass for this mt
                mma16816(acc[mt][0], al, bq[0][0], bq[0][1]);
                mma16816(acc[mt][1], al, bq[0][2], bq[0][3]);
                mma16816(acc[mt][2], al, bq[1][0], bq[1][1]);
                mma16816(acc[mt][3], al, bq[1][2], bq[1][3]);
            }
        }
        if (++sidx == NSTAGE) sidx = 0;
    }

    // epilogue: canonical C layout, float2 stores
    #pragma unroll
    for (int mt = 0; mt < 4; ++mt) {
        int r0 = m0 + wm * 64 + mt * 16 + g;
        #pragma unroll
        for (int nt = 0; nt < 4; ++nt) {
            int c0 = n0 + wn * 32 + nt * 8 + 2 * tg;
            if (c0 < Nc) {
                *(float2*)(Cp + (size_t)r0 * Nc + c0) =
                    make_float2(acc[mt][nt][0], acc[mt][nt][1]);
                *(float2*)(Cp + (size_t)(r0 + 8) * Nc + c0) =
                    make_float2(acc[mt][nt][2], acc[mt][nt][3]);
            }
        }
    }
}

// --------------------- conv + silu + l2norm + beta/g ------------------------
__global__ void __launch_bounds__(512) gdn_convgate(
    const float* __restrict__ qcw, const float* __restrict__ kcw, const float* __restrict__ vcw,
    const float* __restrict__ b_bias, const float* __restrict__ beta_bias,
    const float* __restrict__ A_log, const float* __restrict__ dt_bias)
{
    const int blk = blockIdx.x;
    const int b = blk >> 11, t = blk & 2047;
    const int tid = threadIdx.x;
    const int h = tid >> 5, lane = tid & 31;
    const size_t rowbase = (size_t)blk * NY;

    float qv[2], kv[2];
    float sq = 0.f, sk = 0.f;
    #pragma unroll
    for (int p = 0; p < 2; ++p) {
        int cl = h * 64 + lane + p * 32;
        float aq = 0.f, ak = 0.f;
        #pragma unroll
        for (int j = 0; j < 4; ++j) {
            int tt = t - 3 + j;
            if (tt >= 0) {
                size_t rb = (size_t)(b * 2048 + tt) * NY;
                aq = fmaf(qcw[cl * 4 + j], g_y[rb + cl], aq);
                ak = fmaf(kcw[cl * 4 + j], g_y[rb + 1024 + cl], ak);
            }
        }
        aq = siluf(aq); ak = siluf(ak);
        qv[p] = aq; kv[p] = ak;
        sq = fmaf(aq, aq, sq); sk = fmaf(ak, ak, sk);
    }
    #pragma unroll
    for (int off = 16; off; off >>= 1) {
        sq += __shfl_xor_sync(0xffffffffu, sq, off);
        sk += __shfl_xor_sync(0xffffffffu, sk, off);
    }
    float rq = rsqrtf(sq + 1e-6f) * SCALE_Q;
    float rk = rsqrtf(sk + 1e-6f);
    size_t qkbase = ((size_t)(b * 16 + h) * 2048 + t) * 64;
    g_qT[qkbase + lane]      = qv[0] * rq;
    g_qT[qkbase + lane + 32] = qv[1] * rq;
    g_kT[qkbase + lane]      = kv[0] * rk;
    g_kT[qkbase + lane + 32] = kv[1] * rk;

    size_t vbase = ((size_t)(b * 16 + h) * 2048 + t) * 128;
    #pragma unroll
    for (int p = 0; p < 4; ++p) {
        int d = lane + p * 32;
        int cl = h * 128 + d;
        float av = 0.f;
        #pragma unroll
        for (int j = 0; j < 4; ++j) {
            int tt = t - 3 + j;
            if (tt >= 0)
                av = fmaf(vcw[cl * 4 + j], g_y[(size_t)(b * 2048 + tt) * NY + 2048 + cl], av);
        }
        g_vT[vbase + d] = siluf(av);
    }

    if (tid < 16) {
        float za = g_y[rowbase + 6144 + tid] + dt_bias[tid];
        float sp = (za > 15.f) ? za : log1pf(expf(za));
        g_gdec[(b * 16 + tid) * 2048 + t] = -expf(A_log[tid]) * sp;
        float zb = g_y[rowbase + 6160 + tid] + b_bias[tid] + beta_bias[tid];
        g_beta[(b * 16 + tid) * 2048 + t] = 2.f / (1.f + expf(-zb));
    }
}

// ------------------------------ gated delta scan ----------------------------
// grid (8 dv-chunks of 16, 64 bh), 128 threads: vl = tid>>3 (16 cols), kr = tid&7.
#define STT 32
__global__ void __launch_bounds__(128) gdn_scan()
{
    const int chunk = blockIdx.x;   // 0..7
    const int bh = blockIdx.y;      // 0..63
    const int tid = threadIdx.x;    // 0..127
    const int vl = tid >> 3;        // 0..15
    const int kr = tid & 7;
    const int b = bh >> 4, h = bh & 15;

    __shared__ __align__(16) float sqm[STT][64];
    __shared__ __align__(16) float skm[STT][64];
    __shared__ __align__(16) float svm[STT][16];
    __shared__ __align__(16) float som[STT][16];
    __shared__ float seg[STT];
    __shared__ float sbe[STT];

    float S[8];
    #pragma unroll
    for (int i = 0; i < 8; ++i) S[i] = 0.f;

    const float* qbase = g_qT + (size_t)bh * 2048 * 64;
    const float* kbase = g_kT + (size_t)bh * 2048 * 64;
    const float* vbase = g_vT + (size_t)bh * 2048 * 128 + chunk * 16;
    const float* gbase = g_gdec + bh * 2048;
    const float* bbase = g_beta + bh * 2048;

    const int vr = tid >> 2, vc = (tid & 3) << 2;   // 32 rows x 4 float4s

    for (int tile = 0; tile < 2048 / STT; ++tile) {
        int t0 = tile * STT;
        #pragma unroll
        for (int i = 0; i < 4; ++i) {
            int idx = tid + i * 128;
            int qr = idx >> 4, qc = (idx & 15) << 2;
            *(float4*)&sqm[qr][qc] = *(const float4*)(qbase + (size_t)(t0 + qr) * 64 + qc);
            *(float4*)&skm[qr][qc] = *(const float4*)(kbase + (size_t)(t0 + qr) * 64 + qc);
        }
        *(float4*)&svm[vr][vc] = *(const float4*)(vbase + (size_t)(t0 + vr) * 128 + vc);
        if (tid < STT) {
            seg[tid] = expf(gbase[t0 + tid]);
            sbe[tid] = bbase[t0 + tid];
        }
        __syncthreads();

        #pragma unroll 4
        for (int ts = 0; ts < STT; ++ts) {
            float eg = seg[ts];
            float be = sbe[ts];
            float vv = svm[ts][vl];
            float4 k0 = *(const float4*)&skm[ts][kr * 8];
            float4 k1 = *(const float4*)&skm[ts][kr * 8 + 4];
            float4 q0 = *(const float4*)&sqm[ts][kr * 8];
            float4 q1 = *(const float4*)&sqm[ts][kr * 8 + 4];
            float kk[8] = {k0.x, k0.y, k0.z, k0.w, k1.x, k1.y, k1.z, k1.w};
            float qq[8] = {q0.x, q0.y, q0.z, q0.w, q1.x, q1.y, q1.z, q1.w};
            float mem = 0.f;
            #pragma unroll
            for (int r = 0; r < 8; ++r) {
                S[r] *= eg;
                mem = fmaf(kk[r], S[r], mem);
            }
            mem += __shfl_xor_sync(0xffffffffu, mem, 1);
            mem += __shfl_xor_sync(0xffffffffu, mem, 2);
            mem += __shfl_xor_sync(0xffffffffu, mem, 4);
            float delta = (vv - mem) * be;
            float ov = 0.f;
            #pragma unroll
            for (int r = 0; r < 8; ++r) {
                S[r] = fmaf(kk[r], delta, S[r]);
                ov = fmaf(qq[r], S[r], ov);
            }
            ov += __shfl_xor_sync(0xffffffffu, ov, 1);
            ov += __shfl_xor_sync(0xffffffffu, ov, 2);
            ov += __shfl_xor_sync(0xffffffffu, ov, 4);
            if (kr == 0) som[ts][vl] = ov;
        }
        __syncthreads();

        size_t orow = (size_t)(b * 2048 + t0 + vr) * 2048 + h * 128 + chunk * 16 + vc;
        *(float4*)(g_o + orow) = *(const float4*)&som[vr][vc];
        __syncthreads();
    }
}

// ---------------- RMS-norm over DV + silu(g_out) gate -> fp16 hi/lo ---------
__global__ void __launch_bounds__(256) gdn_normgate()
{
    int gw = blockIdx.x * 8 + (threadIdx.x >> 5);
    int lane = threadIdx.x & 31;
    int m = gw >> 4, h = gw & 15;
    size_t obase = (size_t)m * 2048 + h * 128;
    float v[4]; float ss = 0.f;
    #pragma unroll
    for (int p = 0; p < 4; ++p) {
        v[p] = g_o[obase + lane + p * 32];
        ss = fmaf(v[p], v[p], ss);
    }
    #pragma unroll
    for (int off = 16; off; off >>= 1) ss += __shfl_xor_sync(0xffffffffu, ss, off);
    float r = rsqrtf(ss * (1.f / 128.f) + 1.1920929e-7f);
    size_t ybase = (size_t)m * NY + 4096 + h * 128;
    #pragma unroll
    for (int p = 0; p < 4; ++p) {
        float gz = g_y[ybase + lane + p * 32];
        float val = v[p] * r * siluf(gz);
        __half hh = __float2half_rn(val);
        __half hl = __float2half_rn(val - __half2float(hh));
        g_oh[obase + lane + p * 32] = hh;
        g_ol[obase + lane + p * 32] = hl;
    }
}

// --------------------------------- launch -----------------------------------
extern "C" void kernel_launch(void* const* d_in, const int* in_sizes, int n_in,
                              void* d_out, int out_size)
{
    const float* x         = (const float*)d_in[0];
    const float* qk_w      = (const float*)d_in[1];
    const float* vg_w      = (const float*)d_in[2];
    const float* o_w       = (const float*)d_in[3];
    const float* a_w       = (const float*)d_in[4];
    const float* b_w       = (const float*)d_in[5];
    const float* b_bias    = (const float*)d_in[6];
    const float* beta_bias = (const float*)d_in[7];
    const float* A_log     = (const float*)d_in[8];
    const float* dt_bias   = (const float*)d_in[9];
    const float* qcw       = (const float*)d_in[10];
    const float* kcw       = (const float*)d_in[11];
    const float* vcw       = (const float*)d_in[12];
    float* out = (float*)d_out;

    cudaFuncSetAttribute(gdn_gemm_h2, cudaFuncAttributeMaxDynamicSharedMemorySize, GSMEM);

    // fp16 operand prep
    cvt_x<<<MTOT * KDIM / 4 / 256, 256>>>(x);
    cvt_w<<<NYPAD2 * KDIM / 4 / 256, 256>>>(qk_w, vg_w, a_w, b_w);
    cvt_ow<<<2048 * KDIM / 4 / 256, 256>>>(o_w);

    // GEMM1: y = x @ [qk_w; vg_w; a_w; b_w]^T
    dim3 g1(NYPAD2 / 256, MTOT / 128);
    gdn_gemm_h2<<<g1, 512, GSMEM>>>((float*)0, NY, 1);

    // conv + silu + per-head l2norm + beta/g
    gdn_convgate<<<MTOT, 512>>>(qcw, kcw, vcw, b_bias, beta_bias, A_log, dt_bias);

    // gated delta-rule scan
    dim3 gs(8, 64);
    gdn_scan<<<gs, 128>>>();

    // rms-norm + gate -> fp16 hi/lo
    gdn_normgate<<<MTOT * 16 / 8, 256>>>();

    // GEMM2: out = o @ o_w^T
    dim3 g2(2048 / 256, MTOT / 128);
    gdn_gemm_h2<<<g2, 512, GSMEM>>>(out, 2048, 0);
}